// round 1
// baseline (speedup 1.0000x reference)
#include <cuda_runtime.h>

typedef unsigned long long u64;

#define D_ 128
#define K_ 8
#define TILE_ROWS 64
#define NTHREADS 256
#define W_STRIDE 132   // padded row stride for transposed W (16B-aligned, conflict-light staging)

// smem layout (floats):
//  Wt:     128*132            = 16896
//  xdup:   2 * 64*128*2 (u64) = 32768 floats
//  b,g,be: 3*128              = 384
//  cb:     8*128              = 1024
//  cbinv:  8
#define SMEM_FLOATS (16896 + 32768 + 384 + 1024 + 8)

__device__ __forceinline__ u64 ffma2(u64 a, u64 b, u64 c) {
    u64 d;
    asm("fma.rn.f32x2 %0, %1, %2, %3;" : "=l"(d) : "l"(a), "l"(b), "l"(c));
    return d;
}

__device__ __forceinline__ float2 u2f(u64 v) {
    float2 f;
    asm("mov.b64 {%0, %1}, %2;" : "=f"(f.x), "=f"(f.y) : "l"(v));
    return f;
}

__global__ __launch_bounds__(NTHREADS, 1)
void l1q_kernel(const float* __restrict__ x,
                const float* __restrict__ W,
                const float* __restrict__ bias,
                const float* __restrict__ gamma,
                const float* __restrict__ beta,
                const float* __restrict__ cb,
                float* __restrict__ o_idx,
                float* __restrict__ o_soft,
                float* __restrict__ o_emb,
                float* __restrict__ o_log,
                int B, int NT)
{
    extern __shared__ float sm[];
    float* Wt    = sm;                         // [128][W_STRIDE]
    u64*   xd0   = (u64*)(sm + 16896);         // [64][128] dup pairs
    u64*   xd1   = xd0 + 64 * 128;
    float* sb    = sm + 16896 + 32768;         // 128
    float* sg    = sb + 128;
    float* sbe   = sg + 128;
    float* scb   = sbe + 128;                  // 8*128 raw codebook
    float* scinv = scb + 1024;                 // 8

    const int tid = threadIdx.x;

    // ---- one-time staging: W (transposed), params, codebook ----
    #pragma unroll 4
    for (int i = tid; i < D_ * D_; i += NTHREADS) {
        int j = i >> 7, d = i & 127;
        Wt[d * W_STRIDE + j] = W[i];           // W[j][d] -> Wt[d][j]
    }
    if (tid < D_) { sb[tid] = bias[tid]; sg[tid] = gamma[tid]; sbe[tid] = beta[tid]; }
    for (int i = tid; i < K_ * D_; i += NTHREADS) scb[i] = cb[i];
    __syncthreads();
    if (tid < K_) {
        float s = 0.f;
        #pragma unroll
        for (int d = 0; d < D_; d++) { float v = scb[tid * D_ + d]; s += v * v; }
        scinv[tid] = 1.0f / fmaxf(sqrtf(s), 1e-12f);
    }

    const int cx = tid & 15;        // 16 lanes cover 128 cols (8 each)
    const int ry = tid >> 4;        // 16 row groups x 4 rows = 64-row tile
    const int jbase = cx * 8;

    float4 stg[8];

    auto LOADT = [&](int tt) {
        const float4* src = (const float4*)(x + (size_t)tt * TILE_ROWS * D_);
        #pragma unroll
        for (int kq = 0; kq < 8; kq++) {
            int q = tid + kq * NTHREADS;                 // float4 index in tile
            int row = tt * TILE_ROWS + (q >> 5);
            stg[kq] = (row < B) ? src[q] : make_float4(0.f, 0.f, 0.f, 0.f);
        }
    };
    auto STORET = [&](u64* buf) {
        float4* dst = (float4*)buf;
        #pragma unroll
        for (int kq = 0; kq < 8; kq++) {
            int q = tid + kq * NTHREADS;
            dst[q * 2 + 0] = make_float4(stg[kq].x, stg[kq].x, stg[kq].y, stg[kq].y);
            dst[q * 2 + 1] = make_float4(stg[kq].z, stg[kq].z, stg[kq].w, stg[kq].w);
        }
    };

    int t = blockIdx.x;
    if (t < NT) { LOADT(t); STORET(xd0); }
    __syncthreads();
    int pb = 0;

    const float inv128 = 1.0f / 128.0f;

    for (; t < NT; t += gridDim.x) {
        int tn = t + gridDim.x;
        if (tn < NT) LOADT(tn);                 // prefetch next tile into regs

        // ---- GEMM: 4 rows x 8 cols per thread, f32x2 packed FMA ----
        u64 acc[4][4];
        #pragma unroll
        for (int r = 0; r < 4; r++)
            #pragma unroll
            for (int p = 0; p < 4; p++) acc[r][p] = 0ull;   // (0.f,0.f)

        const u64* xb = (pb ? xd1 : xd0) + (ry * 4) * D_;

        #pragma unroll 4
        for (int d = 0; d < D_; d += 2) {
            ulonglong2 wA01 = *(const ulonglong2*)&Wt[d * W_STRIDE + jbase];
            ulonglong2 wA23 = *(const ulonglong2*)&Wt[d * W_STRIDE + jbase + 4];
            ulonglong2 wB01 = *(const ulonglong2*)&Wt[(d + 1) * W_STRIDE + jbase];
            ulonglong2 wB23 = *(const ulonglong2*)&Wt[(d + 1) * W_STRIDE + jbase + 4];
            #pragma unroll
            for (int r = 0; r < 4; r++) {
                ulonglong2 xp = *(const ulonglong2*)&xb[r * D_ + d];  // (x_d,x_d),(x_d1,x_d1)
                acc[r][0] = ffma2(xp.x, wA01.x, acc[r][0]);
                acc[r][1] = ffma2(xp.x, wA01.y, acc[r][1]);
                acc[r][2] = ffma2(xp.x, wA23.x, acc[r][2]);
                acc[r][3] = ffma2(xp.x, wA23.y, acc[r][3]);
                acc[r][0] = ffma2(xp.y, wB01.x, acc[r][0]);
                acc[r][1] = ffma2(xp.y, wB01.y, acc[r][1]);
                acc[r][2] = ffma2(xp.y, wB23.x, acc[r][2]);
                acc[r][3] = ffma2(xp.y, wB23.y, acc[r][3]);
            }
        }

        // ---- epilogue: LN -> l2norm -> logits -> softmax/argmax -> writes ----
        int rowbase = t * TILE_ROWS + ry * 4;
        #pragma unroll
        for (int r = 0; r < 4; r++) {
            int row = rowbase + r;
            float h[8];
            #pragma unroll
            for (int p = 0; p < 4; p++) {
                float2 f = u2f(acc[r][p]);
                h[2 * p]     = f.x + sb[jbase + 2 * p];
                h[2 * p + 1] = f.y + sb[jbase + 2 * p + 1];
            }
            float s1 = 0.f, s2 = 0.f;
            #pragma unroll
            for (int j = 0; j < 8; j++) { s1 += h[j]; s2 += h[j] * h[j]; }
            #pragma unroll
            for (int m = 1; m <= 8; m <<= 1) {
                s1 += __shfl_xor_sync(0xffffffffu, s1, m);
                s2 += __shfl_xor_sync(0xffffffffu, s2, m);
            }
            float mu   = s1 * inv128;
            float var  = s2 * inv128 - mu * mu;
            float rstd = rsqrtf(var + 1e-5f);

            float hn[8]; float q2 = 0.f;
            #pragma unroll
            for (int j = 0; j < 8; j++) {
                hn[j] = (h[j] - mu) * rstd * sg[jbase + j] + sbe[jbase + j];
                q2 += hn[j] * hn[j];
            }
            #pragma unroll
            for (int m = 1; m <= 8; m <<= 1) q2 += __shfl_xor_sync(0xffffffffu, q2, m);
            float invn = 1.0f / fmaxf(sqrtf(q2), 1e-12f);

            float lg[8];
            #pragma unroll
            for (int k = 0; k < K_; k++) {
                const float4* c = (const float4*)&scb[k * D_ + jbase];
                float4 c0 = c[0], c1 = c[1];
                float a = hn[0] * c0.x + hn[1] * c0.y + hn[2] * c0.z + hn[3] * c0.w
                        + hn[4] * c1.x + hn[5] * c1.y + hn[6] * c1.z + hn[7] * c1.w;
                #pragma unroll
                for (int m = 1; m <= 8; m <<= 1) a += __shfl_xor_sync(0xffffffffu, a, m);
                lg[k] = a * invn * scinv[k];
            }

            float mx = lg[0]; int bi = 0;
            #pragma unroll
            for (int k = 1; k < K_; k++) if (lg[k] > mx) { mx = lg[k]; bi = k; }
            float e[8], ssum = 0.f;
            #pragma unroll
            for (int k = 0; k < K_; k++) { e[k] = __expf(lg[k] - mx); ssum += e[k]; }
            float rs = 1.0f / ssum;

            if (row < B) {
                const float4* cr = (const float4*)&scb[bi * D_ + jbase];
                float4 e0 = cr[0], e1 = cr[1];
                float4* dst = (float4*)&o_emb[(size_t)row * D_ + jbase];
                dst[0] = e0; dst[1] = e1;
                if (cx == 0) {
                    o_idx[row] = (float)bi;
                    *(float4*)&o_soft[(size_t)row * 8]     = make_float4(e[0]*rs, e[1]*rs, e[2]*rs, e[3]*rs);
                    *(float4*)&o_soft[(size_t)row * 8 + 4] = make_float4(e[4]*rs, e[5]*rs, e[6]*rs, e[7]*rs);
                    *(float4*)&o_log [(size_t)row * 8]     = make_float4(lg[0], lg[1], lg[2], lg[3]);
                    *(float4*)&o_log [(size_t)row * 8 + 4] = make_float4(lg[4], lg[5], lg[6], lg[7]);
                }
            }
        }

        if (tn < NT) STORET(pb ? xd0 : xd1);
        __syncthreads();
        pb ^= 1;
    }
}

extern "C" void kernel_launch(void* const* d_in, const int* in_sizes, int n_in,
                              void* d_out, int out_size) {
    const float* x  = (const float*)d_in[0];
    const float* W  = (const float*)d_in[1];
    const float* b  = (const float*)d_in[2];
    const float* g  = (const float*)d_in[3];
    const float* be = (const float*)d_in[4];
    const float* cb = (const float*)d_in[5];

    int B = in_sizes[0] / D_;
    float* out    = (float*)d_out;
    float* o_idx  = out;
    float* o_soft = out + (size_t)B;
    float* o_emb  = o_soft + (size_t)B * K_;
    float* o_log  = o_emb + (size_t)B * D_;

    int NT = (B + TILE_ROWS - 1) / TILE_ROWS;
    int sms = 148;
    cudaDeviceGetAttribute(&sms, cudaDevAttrMultiProcessorCount, 0);
    int grid = (NT < sms) ? NT : sms;

    size_t smem = (size_t)SMEM_FLOATS * sizeof(float);
    cudaFuncSetAttribute(l1q_kernel, cudaFuncAttributeMaxDynamicSharedMemorySize, (int)smem);
    l1q_kernel<<<grid, NTHREADS, smem>>>(x, W, b, g, be, cb,
                                         o_idx, o_soft, o_emb, o_log, B, NT);
}